// round 2
// baseline (speedup 1.0000x reference)
#include <cuda_runtime.h>
#include <cuda_bf16.h>

#define DIM 128
#define VEC 32  // DIM/4 float4 per row

// ---------------------------------------------------------------------------
// Kernel 1 (sub2): one block per type node c. 128 threads, thread d handles
// one float of the row. Sums deg2 gathered entity rows (contiguous edge
// segment [c*deg2, (c+1)*deg2)), adds (N_ENT - deg2), adds the original type
// row, writes out[right_common[c]].
// ---------------------------------------------------------------------------
__global__ void sub2_kernel(const float* __restrict__ emb,
                            const int*   __restrict__ s2row,
                            const int*   __restrict__ lspec,
                            const int*   __restrict__ rcom,
                            float*       __restrict__ out,
                            float n_ent_f, int deg2)
{
    const int c = blockIdx.x;
    const int d = threadIdx.x;            // 0..127
    const int* __restrict__ e = s2row + (size_t)c * deg2;

    float acc = 0.0f;
    #pragma unroll 4
    for (int j = 0; j < deg2; ++j) {
        int src = __ldg(&lspec[__ldg(&e[j])]);
        acc += __ldg(&emb[(size_t)src * DIM + d]);
    }
    const int tgt = rcom[c];
    out[(size_t)tgt * DIM + d] = emb[(size_t)tgt * DIM + d]
                               + acc + (n_ent_f - (float)deg2);
}

// ---------------------------------------------------------------------------
// Kernel 2 (sub3): one warp per entity node n. Each lane owns one float4
// (16 B) of the 512 B row -> perfectly coalesced streaming of emb (read) and
// out (write). The deg3 gathered TYPE rows are read from out (written by
// sub2_kernel); only 1000 distinct rows x 512 B = 512 KB -> L2/L1 resident.
//   sum0 = msg + (N_TYP - deg3)
//   out[right_specific[n]] = emb[right_specific[n]] * (1 - sum0/(1+deg3))
// ---------------------------------------------------------------------------
__global__ void sub3_kernel(const float* __restrict__ emb,
                            const int*   __restrict__ s3row,
                            const int*   __restrict__ lcom,
                            const int*   __restrict__ rspec,
                            float*       __restrict__ out,
                            int n_ent, float n_typ_f, int deg3)
{
    const int warp = threadIdx.x >> 5;
    const int lane = threadIdx.x & 31;
    const int n = blockIdx.x * (blockDim.x >> 5) + warp;
    if (n >= n_ent) return;

    const float4* __restrict__ out4 = (const float4*)out;
    const int* __restrict__ e = s3row + (size_t)n * deg3;

    float4 acc = make_float4(0.f, 0.f, 0.f, 0.f);
    #pragma unroll 4
    for (int j = 0; j < deg3; ++j) {
        int t = __ldg(&lcom[__ldg(&e[j])]);
        float4 v = __ldg(&out4[(size_t)t * VEC + lane]);
        acc.x += v.x; acc.y += v.y; acc.z += v.z; acc.w += v.w;
    }

    const float add     = n_typ_f - (float)deg3;
    const float sum_arr = 1.0f + (float)deg3;
    const int   tgt     = rspec[n];

    float4 iv = __ldg(&((const float4*)emb)[(size_t)tgt * VEC + lane]);
    float4 r;
    r.x = iv.x * (1.0f - (acc.x + add) / sum_arr);
    r.y = iv.y * (1.0f - (acc.y + add) / sum_arr);
    r.z = iv.z * (1.0f - (acc.z + add) / sum_arr);
    r.w = iv.w * (1.0f - (acc.w + add) / sum_arr);

    ((float4*)out)[(size_t)tgt * VEC + lane] = r;
}

// ---------------------------------------------------------------------------
// Launch
// Inputs (metadata order):
//  0 all_node_embedding  f32 [(N_ENT+N_TYP)*D]
//  1 sub2_row  i32   2 sub2_col i32   3 sub3_row i32   4 sub3_col i32
//  5 left_specific i32[N_ENT]   6 right_common i32[N_TYP]
//  7 left_common  i32[N_TYP]    8 right_specific i32[N_ENT]
// Output: full updated embedding, f32 [(N_ENT+N_TYP)*D].
// Every output row is covered: type rows by sub2_kernel, entity rows by
// sub3_kernel (right_common/right_specific are full arange covers).
// ---------------------------------------------------------------------------
extern "C" void kernel_launch(void* const* d_in, const int* in_sizes, int n_in,
                              void* d_out, int out_size)
{
    const float* emb   = (const float*)d_in[0];
    const int*   s2row = (const int*)  d_in[1];
    const int*   s3row = (const int*)  d_in[3];
    const int*   lspec = (const int*)  d_in[5];
    const int*   rcom  = (const int*)  d_in[6];
    const int*   lcom  = (const int*)  d_in[7];
    const int*   rspec = (const int*)  d_in[8];
    float*       out   = (float*)d_out;

    const int n_ent = in_sizes[5];              // 200000
    const int n_typ = in_sizes[6];              // 1000
    const int deg2  = in_sizes[1] / n_typ;      // 64
    const int deg3  = in_sizes[3] / in_sizes[8];// 4

    // sub2: one 128-thread block per type node
    sub2_kernel<<<n_typ, DIM>>>(emb, s2row, lspec, rcom, out,
                                (float)n_ent, deg2);

    // sub3: one warp per entity node, 8 warps/block
    const int warps_per_block = 8;
    const int threads = warps_per_block * 32;
    const int blocks  = (n_ent + warps_per_block - 1) / warps_per_block;
    sub3_kernel<<<blocks, threads>>>(emb, s3row, lcom, rspec, out,
                                     n_ent, (float)n_typ, deg3);
}

// round 3
// speedup vs baseline: 1.4480x; 1.4480x over previous
#include <cuda_runtime.h>
#include <cuda_bf16.h>

#define DIM 128
#define VEC 32  // DIM/4 float4 per row

// ---------------------------------------------------------------------------
// Kernel 1 (sub2): one block of 512 threads per type node c.
// 4 groups x 128 threads; group g sums its slice of the deg2 edge segment,
// partial sums reduced through shared memory. Gathered entity rows are
// read-once -> __ldcs (streaming) so they don't pollute L2 for later kernels.
// ---------------------------------------------------------------------------
__global__ __launch_bounds__(512)
void sub2_kernel(const float* __restrict__ emb,
                 const int*   __restrict__ s2row,
                 const int*   __restrict__ lspec,
                 const int*   __restrict__ rcom,
                 float*       __restrict__ out,
                 float addc, int deg2)
{
    __shared__ float part[4][DIM];

    const int c = blockIdx.x;
    const int d = threadIdx.x & (DIM - 1);   // 0..127
    const int g = threadIdx.x >> 7;          // 0..3

    const int* __restrict__ e = s2row + (size_t)c * deg2;
    const int chunk = deg2 >> 2;
    const int j0 = g * chunk;
    const int j1 = (g == 3) ? deg2 : j0 + chunk;

    float acc = 0.0f;
    #pragma unroll 8
    for (int j = j0; j < j1; ++j) {
        int src = __ldg(&lspec[__ldg(&e[j])]);
        acc += __ldcs(&emb[(size_t)src * DIM + d]);
    }
    part[g][d] = acc;
    __syncthreads();

    if (g == 0) {
        const int tgt = rcom[c];
        float v = __ldg(&emb[(size_t)tgt * DIM + d])
                + part[0][d] + part[1][d] + part[2][d] + part[3][d] + addc;
        // default store: keep the updated type rows resident in L2 for sub3
        out[(size_t)tgt * DIM + d] = v;
    }
}

// ---------------------------------------------------------------------------
// Kernel 2 (sub3) fast path (deg3 == 4): one warp handles TWO entity rows.
// Per warp: 2x int4 edge loads, 8 lcom lookups, 8 type-row gathers (hot,
// cached via __ldg), 2 streaming emb reads (__ldcs), 2 streaming stores
// (__stcs). Everything fully unrolled for maximum MLP.
// ---------------------------------------------------------------------------
__global__ __launch_bounds__(256)
void sub3_kernel_d4(const float4* __restrict__ emb4,
                    const int4*   __restrict__ edges4,   // s3row as int4 per entity
                    const int*    __restrict__ lcom,
                    const int*    __restrict__ rspec,
                    float4*       __restrict__ out4,
                    int n_ent, float add, float inv_sum)
{
    const int warp = threadIdx.x >> 5;
    const int lane = threadIdx.x & 31;
    const int base = (blockIdx.x * (blockDim.x >> 5) + warp) * 2;
    if (base >= n_ent) return;
    const bool has1 = (base + 1) < n_ent;

    // --- edge indices (broadcast loads, 16B vectorized) ---
    int4 e0 = __ldg(&edges4[base]);
    int4 e1 = has1 ? __ldg(&edges4[base + 1]) : e0;

    // --- target rows + streaming entity reads (independent of gathers) ---
    const int r0 = __ldg(&rspec[base]);
    const int r1 = has1 ? __ldg(&rspec[base + 1]) : r0;
    float4 iv0 = __ldcs(&emb4[(size_t)r0 * VEC + lane]);
    float4 iv1 = __ldcs(&emb4[(size_t)r1 * VEC + lane]);

    // --- type indices ---
    int t00 = __ldg(&lcom[e0.x]), t01 = __ldg(&lcom[e0.y]);
    int t02 = __ldg(&lcom[e0.z]), t03 = __ldg(&lcom[e0.w]);
    int t10 = __ldg(&lcom[e1.x]), t11 = __ldg(&lcom[e1.y]);
    int t12 = __ldg(&lcom[e1.z]), t13 = __ldg(&lcom[e1.w]);

    // --- hot type-row gathers (L1/L2 cached) ---
    float4 g00 = __ldg(&out4[(size_t)t00 * VEC + lane]);
    float4 g01 = __ldg(&out4[(size_t)t01 * VEC + lane]);
    float4 g02 = __ldg(&out4[(size_t)t02 * VEC + lane]);
    float4 g03 = __ldg(&out4[(size_t)t03 * VEC + lane]);
    float4 g10 = __ldg(&out4[(size_t)t10 * VEC + lane]);
    float4 g11 = __ldg(&out4[(size_t)t11 * VEC + lane]);
    float4 g12 = __ldg(&out4[(size_t)t12 * VEC + lane]);
    float4 g13 = __ldg(&out4[(size_t)t13 * VEC + lane]);

    float4 a0, a1;
    a0.x = g00.x + g01.x + g02.x + g03.x;
    a0.y = g00.y + g01.y + g02.y + g03.y;
    a0.z = g00.z + g01.z + g02.z + g03.z;
    a0.w = g00.w + g01.w + g02.w + g03.w;
    a1.x = g10.x + g11.x + g12.x + g13.x;
    a1.y = g10.y + g11.y + g12.y + g13.y;
    a1.z = g10.z + g11.z + g12.z + g13.z;
    a1.w = g10.w + g11.w + g12.w + g13.w;

    float4 w0, w1;
    w0.x = iv0.x * (1.0f - (a0.x + add) * inv_sum);
    w0.y = iv0.y * (1.0f - (a0.y + add) * inv_sum);
    w0.z = iv0.z * (1.0f - (a0.z + add) * inv_sum);
    w0.w = iv0.w * (1.0f - (a0.w + add) * inv_sum);
    __stcs(&out4[(size_t)r0 * VEC + lane], w0);

    if (has1) {
        w1.x = iv1.x * (1.0f - (a1.x + add) * inv_sum);
        w1.y = iv1.y * (1.0f - (a1.y + add) * inv_sum);
        w1.z = iv1.z * (1.0f - (a1.z + add) * inv_sum);
        w1.w = iv1.w * (1.0f - (a1.w + add) * inv_sum);
        __stcs(&out4[(size_t)r1 * VEC + lane], w1);
    }
}

// ---------------------------------------------------------------------------
// Kernel 2 generic fallback (any deg3): one warp per entity row.
// ---------------------------------------------------------------------------
__global__ __launch_bounds__(256)
void sub3_kernel_gen(const float* __restrict__ emb,
                     const int*   __restrict__ s3row,
                     const int*   __restrict__ lcom,
                     const int*   __restrict__ rspec,
                     float*       __restrict__ out,
                     int n_ent, float n_typ_f, int deg3)
{
    const int warp = threadIdx.x >> 5;
    const int lane = threadIdx.x & 31;
    const int n = blockIdx.x * (blockDim.x >> 5) + warp;
    if (n >= n_ent) return;

    const float4* __restrict__ out4 = (const float4*)out;
    const int* __restrict__ e = s3row + (size_t)n * deg3;

    float4 acc = make_float4(0.f, 0.f, 0.f, 0.f);
    for (int j = 0; j < deg3; ++j) {
        int t = __ldg(&lcom[__ldg(&e[j])]);
        float4 v = __ldg(&out4[(size_t)t * VEC + lane]);
        acc.x += v.x; acc.y += v.y; acc.z += v.z; acc.w += v.w;
    }
    const float add     = n_typ_f - (float)deg3;
    const float inv_sum = 1.0f / (1.0f + (float)deg3);
    const int   tgt     = rspec[n];
    float4 iv = __ldcs(&((const float4*)emb)[(size_t)tgt * VEC + lane]);
    float4 r;
    r.x = iv.x * (1.0f - (acc.x + add) * inv_sum);
    r.y = iv.y * (1.0f - (acc.y + add) * inv_sum);
    r.z = iv.z * (1.0f - (acc.z + add) * inv_sum);
    r.w = iv.w * (1.0f - (acc.w + add) * inv_sum);
    __stcs(&((float4*)out)[(size_t)tgt * VEC + lane], r);
}

// ---------------------------------------------------------------------------
// Launch. Inputs (metadata order):
//  0 all_node_embedding f32 | 1 sub2_row | 2 sub2_col | 3 sub3_row | 4 sub3_col
//  5 left_specific | 6 right_common | 7 left_common | 8 right_specific
// Output: full updated embedding. Type rows written by sub2, entity rows by
// sub3 (right_common/right_specific together cover every row).
// ---------------------------------------------------------------------------
extern "C" void kernel_launch(void* const* d_in, const int* in_sizes, int n_in,
                              void* d_out, int out_size)
{
    const float* emb   = (const float*)d_in[0];
    const int*   s2row = (const int*)  d_in[1];
    const int*   s3row = (const int*)  d_in[3];
    const int*   lspec = (const int*)  d_in[5];
    const int*   rcom  = (const int*)  d_in[6];
    const int*   lcom  = (const int*)  d_in[7];
    const int*   rspec = (const int*)  d_in[8];
    float*       out   = (float*)d_out;

    const int n_ent = in_sizes[5];
    const int n_typ = in_sizes[6];
    const int deg2  = in_sizes[1] / n_typ;
    const int deg3  = in_sizes[3] / in_sizes[8];

    // ---- sub2: 512 threads/block, 4-way edge split ----
    sub2_kernel<<<n_typ, 512>>>(emb, s2row, lspec, rcom, out,
                                (float)n_ent - (float)deg2, deg2);

    // ---- sub3 ----
    if (deg3 == 4) {
        const int warps_per_block = 8;
        const int ents_per_block  = warps_per_block * 2;
        const int blocks = (n_ent + ents_per_block - 1) / ents_per_block;
        sub3_kernel_d4<<<blocks, warps_per_block * 32>>>(
            (const float4*)emb, (const int4*)s3row, lcom, rspec,
            (float4*)out, n_ent,
            (float)n_typ - 4.0f, 1.0f / 5.0f);
    } else {
        const int warps_per_block = 8;
        const int blocks = (n_ent + warps_per_block - 1) / warps_per_block;
        sub3_kernel_gen<<<blocks, warps_per_block * 32>>>(
            emb, s3row, lcom, rspec, out, n_ent, (float)n_typ, deg3);
    }
}